// round 4
// baseline (speedup 1.0000x reference)
#include <cuda_runtime.h>

#define NN 100000
#define NE 1200000
#define EPSF 1e-5f
#define NBLK 391  // ceil(NN/256)

// ---------------- scratch (device globals; no allocations) ----------------
__device__ int   g_cnt[NN];
__device__ int   g_rowptr[NN + 1];
__device__ int   g_cursor[NN];
__device__ int   g_blocksum[NBLK];
__device__ int   g_blockoff[NBLK];
__device__ int   g_csr[NE];
__device__ float g_agg1[NN * 64];
__device__ float g_hpre[NN * 128];
__device__ float g_t2[NN * 64];
__device__ float g_p2[NN * 64];
__device__ float g_x0pre[NN * 64];
__device__ float g_s1[128], g_ss1[128];
__device__ float g_s2[64], g_ss2[64];
__device__ float g_W1Th[128 * 128], g_W1Tl[128 * 128];  // [k][o] hi/lo tf32 split
__device__ float g_W2Th[128 * 128], g_W2Tl[128 * 128];
__device__ int   g_is64;

__device__ __forceinline__ unsigned tf32_rna(float a) {
    unsigned r;
    asm("cvt.rna.tf32.f32 %0, %1;" : "=r"(r) : "f"(a));
    return r;
}

__device__ __forceinline__ void split_tf32(float a, unsigned& hi, unsigned& lo) {
    unsigned h = tf32_rna(a);
    float l = a - __uint_as_float(h);
    hi = h;
    lo = tf32_rna(l);
}

__device__ __forceinline__ void mma_tf32(float* d, const unsigned* a, unsigned b0, unsigned b1) {
    asm volatile(
        "mma.sync.aligned.m16n8k8.row.col.f32.tf32.tf32.f32 "
        "{%0,%1,%2,%3},{%4,%5,%6,%7},{%8,%9},{%0,%1,%2,%3};"
        : "+f"(d[0]), "+f"(d[1]), "+f"(d[2]), "+f"(d[3])
        : "r"(a[0]), "r"(a[1]), "r"(a[2]), "r"(a[3]), "r"(b0), "r"(b1));
}

// ---------------- K0: init + weight transpose/split + dtype detect ----------------
__global__ void init_kernel(const int* __restrict__ ei,
                            const float* __restrict__ Wl1, const float* __restrict__ Wr1,
                            const float* __restrict__ Wl2, const float* __restrict__ Wr2) {
    int i = blockIdx.x * blockDim.x + threadIdx.x;
    int stride = gridDim.x * blockDim.x;
    for (int j = i; j < NN; j += stride) g_cnt[j] = 0;
    if (i < 16384) {
        int k = i >> 7, o = i & 127;
        float w1 = (k < 64) ? Wl1[o * 64 + k] : Wr1[o * 64 + (k - 64)];
        float w2 = (o < 64) ? Wl2[o * 128 + k] : Wr2[(o - 64) * 128 + k];
        unsigned h, l;
        split_tf32(w1, h, l);
        g_W1Th[i] = __uint_as_float(h); g_W1Tl[i] = __uint_as_float(l);
        split_tf32(w2, h, l);
        g_W2Th[i] = __uint_as_float(h); g_W2Tl[i] = __uint_as_float(l);
    }
    if (i < 128) { g_s1[i] = 0.f; g_ss1[i] = 0.f; }
    if (i < 64)  { g_s2[i] = 0.f; g_ss2[i] = 0.f; }
    if (i == 0) {
        int z = 0;
        #pragma unroll
        for (int k = 1; k < 16; k += 2) z |= ei[k];
        g_is64 = (z == 0) ? 1 : 0;
    }
}

// ---------------- CSR build ----------------
__global__ __launch_bounds__(256) void hist_kernel(const int* __restrict__ ei) {
    int e = blockIdx.x * 256 + threadIdx.x;
    if (e >= NE) return;
    int d = g_is64 ? ei[2 * (NE + e)] : ei[NE + e];
    atomicAdd(&g_cnt[d], 1);
}

__global__ __launch_bounds__(256) void scan_a_kernel() {
    __shared__ int s[256];
    int t = threadIdx.x;
    int i = blockIdx.x * 256 + t;
    s[t] = (i < NN) ? g_cnt[i] : 0;
    __syncthreads();
    for (int off = 128; off; off >>= 1) {
        if (t < off) s[t] += s[t + off];
        __syncthreads();
    }
    if (t == 0) g_blocksum[blockIdx.x] = s[0];
}

__global__ __launch_bounds__(512) void scan_b_kernel() {
    __shared__ int s[512];
    int t = threadIdx.x;
    int v = (t < NBLK) ? g_blocksum[t] : 0;
    s[t] = v;
    __syncthreads();
    for (int off = 1; off < 512; off <<= 1) {
        int x = (t >= off) ? s[t - off] : 0;
        __syncthreads();
        s[t] += x;
        __syncthreads();
    }
    if (t < NBLK) g_blockoff[t] = s[t] - v;
}

__global__ __launch_bounds__(256) void scan_c_kernel() {
    __shared__ int s[256];
    int t = threadIdx.x;
    int i = blockIdx.x * 256 + t;
    int v = (i < NN) ? g_cnt[i] : 0;
    s[t] = v;
    __syncthreads();
    for (int off = 1; off < 256; off <<= 1) {
        int x = (t >= off) ? s[t - off] : 0;
        __syncthreads();
        s[t] += x;
        __syncthreads();
    }
    int excl = g_blockoff[blockIdx.x] + s[t] - v;
    if (i < NN) { g_rowptr[i] = excl; g_cursor[i] = excl; }
    if (i == 0) g_rowptr[NN] = NE;
}

__global__ __launch_bounds__(256) void fill_kernel(const int* __restrict__ ei) {
    int e = blockIdx.x * 256 + threadIdx.x;
    if (e >= NE) return;
    int s, d;
    if (g_is64) { s = ei[2 * e]; d = ei[2 * (NE + e)]; }
    else        { s = ei[e];     d = ei[NE + e]; }
    int pos = atomicAdd(&g_cursor[d], 1);
    g_csr[pos] = s;
}

// ---------------- K4: aggregate x -> agg1 (warp per node) ----------------
__global__ __launch_bounds__(256) void agg1_kernel(const float* __restrict__ x) {
    int node = (blockIdx.x * 256 + threadIdx.x) >> 5;
    if (node >= NN) return;
    int lane = threadIdx.x & 31;
    int c4 = lane & 15, half = lane >> 4;
    int start = g_rowptr[node], end = g_rowptr[node + 1];
    float4 acc = make_float4(0.f, 0.f, 0.f, 0.f);
    for (int e = start + half; e < end; e += 2) {
        int s = __ldg(&g_csr[e]);
        float4 v = *(const float4*)&x[(size_t)s * 64 + c4 * 4];
        acc.x += v.x; acc.y += v.y; acc.z += v.z; acc.w += v.w;
    }
    acc.x += __shfl_xor_sync(0xFFFFFFFFu, acc.x, 16);
    acc.y += __shfl_xor_sync(0xFFFFFFFFu, acc.y, 16);
    acc.z += __shfl_xor_sync(0xFFFFFFFFu, acc.z, 16);
    acc.w += __shfl_xor_sync(0xFFFFFFFFu, acc.w, 16);
    if (half == 0)
        *(float4*)&g_agg1[(size_t)node * 64 + c4 * 4] = acc;
}

// ---------------- K5: layer-1 tensor-core GEMM (3xTF32) ----------------
#define SMEM_FLOATS (128 * 132 + 2 * 8 * 132)

__global__ __launch_bounds__(256, 2) void layer1_mma(const float* __restrict__ x,
                                                     const float* __restrict__ bl1) {
    extern __shared__ float sm[];
    float* in_s = sm;                   // [128][132]
    float* wh_s = sm + 128 * 132;       // [8][132]
    float* wl_s = wh_s + 8 * 132;
    __shared__ float inv_sh[128];

    int t = threadIdx.x;
    int node0 = blockIdx.x * 128;
    if (t < 128) {
        int n = node0 + t;
        inv_sh[t] = (n < NN) ? 1.0f / fmaxf((float)(g_rowptr[n + 1] - g_rowptr[n]), 1.0f) : 0.f;
    }
    __syncthreads();

    for (int idx = t; idx < 128 * 64; idx += 256) {
        int ni = idx >> 6, k2 = idx & 63;
        int node = node0 + ni;
        float2 v = make_float2(0.f, 0.f);
        if (node < NN) {
            if (k2 < 32) {
                v = *(const float2*)&g_agg1[(size_t)node * 64 + k2 * 2];
                float s = inv_sh[ni];
                v.x *= s; v.y *= s;
            } else {
                v = *(const float2*)&x[(size_t)node * 64 + (k2 - 32) * 2];
            }
        }
        *(float2*)&in_s[ni * 132 + k2 * 2] = v;
    }

    int lane = t & 31, w = t >> 5;
    int wm = w >> 1, wn = w & 1;
    int g = lane >> 2, t4 = lane & 3;
    float acc[2][8][4];
    #pragma unroll
    for (int a = 0; a < 2; a++)
        #pragma unroll
        for (int b = 0; b < 8; b++)
            #pragma unroll
            for (int c = 0; c < 4; c++) acc[a][b][c] = 0.f;

    for (int ks = 0; ks < 16; ks++) {
        __syncthreads();
        const float* Wh = g_W1Th + ks * 8 * 128;
        const float* Wl = g_W1Tl + ks * 8 * 128;
        for (int idx = t; idx < 512; idx += 256) {
            int kk = idx >> 6, o2 = idx & 63;
            *(float2*)&wh_s[kk * 132 + o2 * 2] = *(const float2*)&Wh[kk * 128 + o2 * 2];
            *(float2*)&wl_s[kk * 132 + o2 * 2] = *(const float2*)&Wl[kk * 128 + o2 * 2];
        }
        __syncthreads();

        unsigned ah[2][4], al[2][4];
        #pragma unroll
        for (int mt = 0; mt < 2; mt++) {
            int r = wm * 32 + mt * 16 + g;
            float a0 = in_s[r * 132 + ks * 8 + t4];
            float a1 = in_s[(r + 8) * 132 + ks * 8 + t4];
            float a2 = in_s[r * 132 + ks * 8 + t4 + 4];
            float a3 = in_s[(r + 8) * 132 + ks * 8 + t4 + 4];
            split_tf32(a0, ah[mt][0], al[mt][0]);
            split_tf32(a1, ah[mt][1], al[mt][1]);
            split_tf32(a2, ah[mt][2], al[mt][2]);
            split_tf32(a3, ah[mt][3], al[mt][3]);
        }
        #pragma unroll
        for (int nt = 0; nt < 8; nt++) {
            int c = wn * 64 + nt * 8 + g;
            unsigned bh0 = __float_as_uint(wh_s[t4 * 132 + c]);
            unsigned bh1 = __float_as_uint(wh_s[(t4 + 4) * 132 + c]);
            unsigned bL0 = __float_as_uint(wl_s[t4 * 132 + c]);
            unsigned bL1 = __float_as_uint(wl_s[(t4 + 4) * 132 + c]);
            #pragma unroll
            for (int mt = 0; mt < 2; mt++) {
                mma_tf32(acc[mt][nt], ah[mt], bh0, bh1);
                mma_tf32(acc[mt][nt], al[mt], bh0, bh1);
                mma_tf32(acc[mt][nt], ah[mt], bL0, bL1);
            }
        }
    }

    #pragma unroll
    for (int mt = 0; mt < 2; mt++) {
        #pragma unroll
        for (int nt = 0; nt < 8; nt++) {
            int rr = wm * 32 + mt * 16 + g;
            int col = wn * 64 + nt * 8 + 2 * t4;
            float b0 = bl1[col], b1 = bl1[col + 1];
            int n0_ = node0 + rr, n1_ = node0 + rr + 8;
            if (n0_ < NN)
                *(float2*)&g_hpre[(size_t)n0_ * 128 + col] =
                    make_float2(acc[mt][nt][0] + b0, acc[mt][nt][1] + b1);
            if (n1_ < NN)
                *(float2*)&g_hpre[(size_t)n1_ * 128 + col] =
                    make_float2(acc[mt][nt][2] + b0, acc[mt][nt][3] + b1);
        }
    }
}

// ---------------- K5b: BN1 stats over hpre ----------------
__global__ __launch_bounds__(256) void bn1stats_kernel() {
    int t = threadIdx.x;
    int col = t & 127, half = t >> 7;
    float s = 0.f, ss = 0.f;
    for (int node = blockIdx.x * 2 + half; node < NN; node += gridDim.x * 2) {
        float v = g_hpre[(size_t)node * 128 + col];
        s += v; ss += v * v;
    }
    __shared__ float shs[2][128], shss[2][128];
    shs[half][col] = s;
    shss[half][col] = ss;
    __syncthreads();
    if (half == 0) {
        atomicAdd(&g_s1[col], shs[0][col] + shs[1][col]);
        atomicAdd(&g_ss1[col], shss[0][col] + shss[1][col]);
    }
}

// ---------------- K6: BN1+ReLU + layer-2 tensor-core GEMM (3xTF32) ----------------
__global__ __launch_bounds__(256, 2) void layer2_mma(const float* __restrict__ bl2,
                                                     const float* __restrict__ g1,
                                                     const float* __restrict__ b1) {
    extern __shared__ float sm[];
    float* in_s = sm;
    float* wh_s = sm + 128 * 132;
    float* wl_s = wh_s + 8 * 132;
    __shared__ float sc_sh[128], sh_sh[128];

    int t = threadIdx.x;
    int node0 = blockIdx.x * 128;
    const float invN = 1.0f / (float)NN;
    if (t < 128) {
        float mu = g_s1[t] * invN;
        float var = g_ss1[t] * invN - mu * mu;
        float sc = g1[t] * rsqrtf(var + EPSF);
        sc_sh[t] = sc;
        sh_sh[t] = b1[t] - mu * sc;
    }
    __syncthreads();

    for (int idx = t; idx < 128 * 64; idx += 256) {
        int ni = idx >> 6, k2 = idx & 63;
        int node = node0 + ni;
        float2 v = make_float2(0.f, 0.f);
        if (node < NN) {
            v = *(const float2*)&g_hpre[(size_t)node * 128 + k2 * 2];
            int c = k2 * 2;
            v.x = fmaxf(v.x * sc_sh[c] + sh_sh[c], 0.f);
            v.y = fmaxf(v.y * sc_sh[c + 1] + sh_sh[c + 1], 0.f);
        }
        *(float2*)&in_s[ni * 132 + k2 * 2] = v;
    }

    int lane = t & 31, w = t >> 5;
    int wm = w >> 1, wn = w & 1;
    int g = lane >> 2, t4 = lane & 3;
    float acc[2][8][4];
    #pragma unroll
    for (int a = 0; a < 2; a++)
        #pragma unroll
        for (int b = 0; b < 8; b++)
            #pragma unroll
            for (int c = 0; c < 4; c++) acc[a][b][c] = 0.f;

    for (int ks = 0; ks < 16; ks++) {
        __syncthreads();
        const float* Wh = g_W2Th + ks * 8 * 128;
        const float* Wl = g_W2Tl + ks * 8 * 128;
        for (int idx = t; idx < 512; idx += 256) {
            int kk = idx >> 6, o2 = idx & 63;
            *(float2*)&wh_s[kk * 132 + o2 * 2] = *(const float2*)&Wh[kk * 128 + o2 * 2];
            *(float2*)&wl_s[kk * 132 + o2 * 2] = *(const float2*)&Wl[kk * 128 + o2 * 2];
        }
        __syncthreads();

        unsigned ah[2][4], al[2][4];
        #pragma unroll
        for (int mt = 0; mt < 2; mt++) {
            int r = wm * 32 + mt * 16 + g;
            float a0 = in_s[r * 132 + ks * 8 + t4];
            float a1 = in_s[(r + 8) * 132 + ks * 8 + t4];
            float a2 = in_s[r * 132 + ks * 8 + t4 + 4];
            float a3 = in_s[(r + 8) * 132 + ks * 8 + t4 + 4];
            split_tf32(a0, ah[mt][0], al[mt][0]);
            split_tf32(a1, ah[mt][1], al[mt][1]);
            split_tf32(a2, ah[mt][2], al[mt][2]);
            split_tf32(a3, ah[mt][3], al[mt][3]);
        }
        #pragma unroll
        for (int nt = 0; nt < 8; nt++) {
            int c = wn * 64 + nt * 8 + g;
            unsigned bh0 = __float_as_uint(wh_s[t4 * 132 + c]);
            unsigned bh1 = __float_as_uint(wh_s[(t4 + 4) * 132 + c]);
            unsigned bL0 = __float_as_uint(wl_s[t4 * 132 + c]);
            unsigned bL1 = __float_as_uint(wl_s[(t4 + 4) * 132 + c]);
            #pragma unroll
            for (int mt = 0; mt < 2; mt++) {
                mma_tf32(acc[mt][nt], ah[mt], bh0, bh1);
                mma_tf32(acc[mt][nt], al[mt], bh0, bh1);
                mma_tf32(acc[mt][nt], ah[mt], bL0, bL1);
            }
        }
    }

    #pragma unroll
    for (int mt = 0; mt < 2; mt++) {
        #pragma unroll
        for (int nt = 0; nt < 8; nt++) {
            int rr = wm * 32 + mt * 16 + g;
            int col = wn * 64 + nt * 8 + 2 * t4;
            int n0_ = node0 + rr, n1_ = node0 + rr + 8;
            if (col < 64) {
                if (n0_ < NN)
                    *(float2*)&g_t2[(size_t)n0_ * 64 + col] =
                        make_float2(acc[mt][nt][0], acc[mt][nt][1]);
                if (n1_ < NN)
                    *(float2*)&g_t2[(size_t)n1_ * 64 + col] =
                        make_float2(acc[mt][nt][2], acc[mt][nt][3]);
            } else {
                int cc = col - 64;
                float b0 = bl2[cc], b1 = bl2[cc + 1];
                if (n0_ < NN)
                    *(float2*)&g_p2[(size_t)n0_ * 64 + cc] =
                        make_float2(acc[mt][nt][0] + b0, acc[mt][nt][1] + b1);
                if (n1_ < NN)
                    *(float2*)&g_p2[(size_t)n1_ * 64 + cc] =
                        make_float2(acc[mt][nt][2] + b0, acc[mt][nt][3] + b1);
            }
        }
    }
}

// ---------------- K7: aggregate t2 + mean + p2 -> x0pre, BN2 stats ----------------
__global__ __launch_bounds__(256) void agg2_kernel() {
    __shared__ float s2s[64], ss2s[64];
    int t = threadIdx.x;
    if (t < 64) { s2s[t] = 0.f; ss2s[t] = 0.f; }
    __syncthreads();

    int node = (blockIdx.x * 256 + t) >> 5;
    int lane = t & 31;
    int c4 = lane & 15, half = lane >> 4;
    if (node < NN) {
        int start = g_rowptr[node], end = g_rowptr[node + 1];
        float4 acc = make_float4(0.f, 0.f, 0.f, 0.f);
        for (int e = start + half; e < end; e += 2) {
            int s = __ldg(&g_csr[e]);
            float4 v = *(const float4*)&g_t2[(size_t)s * 64 + c4 * 4];
            acc.x += v.x; acc.y += v.y; acc.z += v.z; acc.w += v.w;
        }
        acc.x += __shfl_xor_sync(0xFFFFFFFFu, acc.x, 16);
        acc.y += __shfl_xor_sync(0xFFFFFFFFu, acc.y, 16);
        acc.z += __shfl_xor_sync(0xFFFFFFFFu, acc.z, 16);
        acc.w += __shfl_xor_sync(0xFFFFFFFFu, acc.w, 16);
        if (half == 0) {
            float invd = 1.0f / fmaxf((float)(end - start), 1.0f);
            float4 p = *(const float4*)&g_p2[(size_t)node * 64 + c4 * 4];
            float4 v = make_float4(acc.x * invd + p.x, acc.y * invd + p.y,
                                   acc.z * invd + p.z, acc.w * invd + p.w);
            *(float4*)&g_x0pre[(size_t)node * 64 + c4 * 4] = v;
            atomicAdd(&s2s[c4 * 4 + 0], v.x);
            atomicAdd(&s2s[c4 * 4 + 1], v.y);
            atomicAdd(&s2s[c4 * 4 + 2], v.z);
            atomicAdd(&s2s[c4 * 4 + 3], v.w);
            atomicAdd(&ss2s[c4 * 4 + 0], v.x * v.x);
            atomicAdd(&ss2s[c4 * 4 + 1], v.y * v.y);
            atomicAdd(&ss2s[c4 * 4 + 2], v.z * v.z);
            atomicAdd(&ss2s[c4 * 4 + 3], v.w * v.w);
        }
    }
    __syncthreads();
    if (t < 64) {
        atomicAdd(&g_s2[t], s2s[t]);
        atomicAdd(&g_ss2[t], ss2s[t]);
    }
}

// ---------------- K8: BN2+ReLU -> x0 out; fc + softmax -> x1 out ----------------
__global__ __launch_bounds__(256) void final_kernel(float* __restrict__ out,
                                                    const float* __restrict__ g2,
                                                    const float* __restrict__ b2,
                                                    const float* __restrict__ Wfc,
                                                    const float* __restrict__ bfc) {
    int node = blockIdx.x * 8 + (threadIdx.x >> 5);
    int lane = threadIdx.x & 31;
    if (node >= NN) return;
    const float invN = 1.0f / (float)NN;
    float x0v[2];
    #pragma unroll
    for (int j = 0; j < 2; j++) {
        int c = lane + 32 * j;
        float mu = g_s2[c] * invN;
        float var = g_ss2[c] * invN - mu * mu;
        float v = g_x0pre[(size_t)node * 64 + c];
        v = g2[c] * (v - mu) * rsqrtf(var + EPSF) + b2[c];
        v = fmaxf(v, 0.f);
        x0v[j] = v;
        out[(size_t)node * 64 + c] = v;
    }
    float l0 = x0v[0] * Wfc[lane] + x0v[1] * Wfc[lane + 32];
    float l1 = x0v[0] * Wfc[64 + lane] + x0v[1] * Wfc[96 + lane];
    #pragma unroll
    for (int o = 16; o; o >>= 1) {
        l0 += __shfl_down_sync(0xFFFFFFFFu, l0, o);
        l1 += __shfl_down_sync(0xFFFFFFFFu, l1, o);
    }
    if (lane == 0) {
        l0 += bfc[0];
        l1 += bfc[1];
        float m = fmaxf(l0, l1);
        float e0 = __expf(l0 - m), e1 = __expf(l1 - m);
        float inv = 1.0f / (e0 + e1);
        out[(size_t)NN * 64 + node * 2 + 0] = e0 * inv;
        out[(size_t)NN * 64 + node * 2 + 1] = e1 * inv;
    }
}

// ---------------- launch ----------------
extern "C" void kernel_launch(void* const* d_in, const int* in_sizes, int n_in,
                              void* d_out, int out_size) {
    const float* x   = (const float*)d_in[0];
    const int*   ei  = (const int*)d_in[1];
    const float* Wl1 = (const float*)d_in[2];
    const float* bl1 = (const float*)d_in[3];
    const float* Wr1 = (const float*)d_in[4];
    const float* g1  = (const float*)d_in[5];
    const float* b1  = (const float*)d_in[6];
    const float* Wl2 = (const float*)d_in[7];
    const float* bl2 = (const float*)d_in[8];
    const float* Wr2 = (const float*)d_in[9];
    const float* g2  = (const float*)d_in[10];
    const float* b2  = (const float*)d_in[11];
    const float* Wfc = (const float*)d_in[12];
    const float* bfc = (const float*)d_in[13];
    float* out = (float*)d_out;

    const int smem_bytes = SMEM_FLOATS * 4;
    static int configured = 0;
    if (!configured) {
        cudaFuncSetAttribute(layer1_mma, cudaFuncAttributeMaxDynamicSharedMemorySize, smem_bytes);
        cudaFuncSetAttribute(layer2_mma, cudaFuncAttributeMaxDynamicSharedMemorySize, smem_bytes);
        configured = 1;
    }

    init_kernel<<<512, 256>>>(ei, Wl1, Wr1, Wl2, Wr2);
    hist_kernel<<<(NE + 255) / 256, 256>>>(ei);
    scan_a_kernel<<<NBLK, 256>>>();
    scan_b_kernel<<<1, 512>>>();
    scan_c_kernel<<<NBLK, 256>>>();
    fill_kernel<<<(NE + 255) / 256, 256>>>(ei);
    agg1_kernel<<<(NN * 32 + 255) / 256, 256>>>(x);
    layer1_mma<<<(NN + 127) / 128, 256, smem_bytes>>>(x, bl1);
    bn1stats_kernel<<<512, 256>>>();
    layer2_mma<<<(NN + 127) / 128, 256, smem_bytes>>>(bl2, g1, b1);
    agg2_kernel<<<(NN * 32 + 255) / 256, 256>>>();
    final_kernel<<<(NN + 7) / 8, 256>>>(out, g2, b2, Wfc, bfc);
}